// round 12
// baseline (speedup 1.0000x reference)
#include <cuda_runtime.h>
#include <cstdint>

// ---------------------------------------------------------------------------
// Seq2seq BiLSTM (encoder 336 + autoregressive decoder 24), persistent kernel.
//
// Grid = 128 CTAs = 2 dirs x 4 batch-tiles(32) x 16 j-tiles(16), 128 thr/CTA.
// Thread owns 4 batch rows x 4 gates of one hidden unit (f32x2 gate pairs).
// Fine-grained peer pipelining: each peer CTA's 16-col h slice is polled,
// staged (per-warp, syncwarp only) and GEMMed independently, with the next
// slice's LDG prefetched under the current slice's GEMM. Own slice is staged
// into smem at pointwise time (no global round-trip). One __syncthreads per
// round (at the flag release). g_h double-buffered by step parity.
// ---------------------------------------------------------------------------

#define NBLK 128
#define NTHR 128

namespace {
constexpr int BATCH = 128;
constexpr int SEQLEN = 336;
constexpr int PRED = 24;
constexpr int IN = 64;
constexpr int HID = 256;
constexpr int KTOT = IN + HID;          // 320
constexpr int WS2 = 34;                 // W plane row stride (floats)
constexpr int AS = 328;                 // A row stride (floats)
constexpr int SMEM_FLOATS = 2 * KTOT * WS2 + 32 * AS + 64;  // 32320
constexpr int SMEM_BYTES = SMEM_FLOATS * 4;                 // 129280 B
}

__device__ float g_h[2][2 * BATCH * HID];       // [parity][dir*BATCH+b][HID]
__device__ float g_y[PRED * BATCH * IN];
__device__ int   g_flags[NBLK];

using u64 = unsigned long long;

__device__ __forceinline__ int ld_acq(const int* p) {
    int v;
    asm volatile("ld.global.acquire.gpu.b32 %0, [%1];" : "=r"(v) : "l"(p) : "memory");
    return v;
}
__device__ __forceinline__ void st_rel(int* p, int v) {
    asm volatile("st.global.release.gpu.b32 [%0], %1;" :: "l"(p), "r"(v) : "memory");
}
__device__ __forceinline__ u64 ffma2(u64 a, u64 b, u64 c) {
    u64 d;
    asm("fma.rn.f32x2 %0, %1, %2, %3;" : "=l"(d) : "l"(a), "l"(b), "l"(c));
    return d;
}
__device__ __forceinline__ u64 pack2(float lo, float hi) {
    u64 d;
    asm("mov.b64 %0, {%1, %2};" : "=l"(d) : "f"(lo), "f"(hi));
    return d;
}
__device__ __forceinline__ void unpack2(float& lo, float& hi, u64 v) {
    asm("mov.b64 {%0, %1}, %2;" : "=f"(lo), "=f"(hi) : "l"(v));
}
__device__ __forceinline__ float fsig(float x) {
    return __fdividef(1.0f, 1.0f + __expf(-x));
}
__device__ __forceinline__ float ftanh(float x) {
    float ax = fabsf(x);
    float t = __expf(-2.0f * ax);
    float r = __fdividef(1.0f - t, 1.0f + t);
    return copysignf(r, x);
}

__device__ __forceinline__ void release(int v) {
    __syncthreads();
    if (threadIdx.x == 0) st_rel(&g_flags[blockIdx.x], v);
}
__device__ __forceinline__ void waitf(int base, int cnt, int v) {
    if (threadIdx.x < cnt) {
        const int* p = &g_flags[base + threadIdx.x];
        while (ld_acq(p) < v) { }
    }
    __syncthreads();
}
// All lanes poll one flag (broadcast load) until it reaches v.
__device__ __forceinline__ void pollflag(int idx, int v) {
    const int* p = &g_flags[idx];
    while (ld_acq(p) < v) { }
}

// W planes: W01[k*WS2 + jj*2 + g] (gates i,f), W23 (gates g,o). Conflict-free
// LDS.64 (2-float spacing covers all 32 banks once across tj=0..15).
__device__ void load_phase_weights(float* W01, float* W23, float* bsum,
                                   const float* __restrict__ Wih,
                                   const float* __restrict__ Whh,
                                   const float* __restrict__ bih,
                                   const float* __restrict__ bhh,
                                   int d, int j0) {
    for (int idx = threadIdx.x; idx < 64 * KTOT; idx += NTHR) {
        int c = idx / KTOT;
        int k = idx - c * KTOT;
        int jj = c >> 2, g = c & 3;
        int row = g * 256 + j0 + jj;
        float v = (k < IN) ? Wih[(d * 1024 + row) * IN + k]
                           : Whh[(d * 1024 + row) * HID + (k - IN)];
        if (g < 2) W01[k * WS2 + jj * 2 + g] = v;
        else       W23[k * WS2 + jj * 2 + (g - 2)] = v;
    }
    for (int c = threadIdx.x; c < 64; c += NTHR) {
        int jj = c >> 2, g = c & 3;
        int row = g * 256 + j0 + jj;
        bsum[c] = bih[d * 1024 + row] + bhh[d * 1024 + row];
    }
}

// 16-k GEMM span starting at k0 (fully unrolled).
__device__ __forceinline__ void gemm16(const float* Asm, const float* W01,
                                       const float* W23, int tj, int tb,
                                       int k0, u64 acc[4][2]) {
    const float* A0 = Asm + (tb * 4) * AS;
#pragma unroll
    for (int kk4 = 0; kk4 < 16; kk4 += 4) {
        int k = k0 + kk4;
        float4 a0 = *(const float4*)(A0 + k);
        float4 a1 = *(const float4*)(A0 + AS + k);
        float4 a2 = *(const float4*)(A0 + 2 * AS + k);
        float4 a3 = *(const float4*)(A0 + 3 * AS + k);
        float av[4][4] = {{a0.x, a0.y, a0.z, a0.w},
                          {a1.x, a1.y, a1.z, a1.w},
                          {a2.x, a2.y, a2.z, a2.w},
                          {a3.x, a3.y, a3.z, a3.w}};
#pragma unroll
        for (int kk = 0; kk < 4; kk++) {
            u64 w01 = *(const u64*)(W01 + (k + kk) * WS2 + tj * 2);
            u64 w23 = *(const u64*)(W23 + (k + kk) * WS2 + tj * 2);
#pragma unroll
            for (int bi = 0; bi < 4; bi++) {
                u64 ad = pack2(av[bi][kk], av[bi][kk]);
                acc[bi][0] = ffma2(ad, w01, acc[bi][0]);
                acc[bi][1] = ffma2(ad, w23, acc[bi][1]);
            }
        }
    }
}

// PRE: per-warp stage of x rows [8w,8w+8) (cols 0..63), bias init, x-GEMM.
__device__ __forceinline__ void cell_pre(const float* __restrict__ src,
                                         int rowStride, int b0,
                                         const float* W01, const float* W23,
                                         float* Asm, const float* bsum,
                                         u64 acc[4][2], int wid, int lane,
                                         int tj, int tb) {
#pragma unroll
    for (int it = 0; it < 4; it++) {
        int idx = lane + 32 * it;               // 0..127
        int row = 8 * wid + (idx >> 4);
        int f4 = idx & 15;
        float4 v = __ldcg((const float4*)(src + (size_t)(b0 + row) * rowStride) + f4);
        *(float4*)(Asm + row * AS + f4 * 4) = v;
    }
    __syncwarp();

    {
        float4 bv = *(const float4*)(bsum + tj * 4);
        u64 b01 = pack2(bv.x, bv.y);
        u64 b23 = pack2(bv.z, bv.w);
#pragma unroll
        for (int bi = 0; bi < 4; bi++) { acc[bi][0] = b01; acc[bi][1] = b23; }
    }
#pragma unroll
    for (int k0 = 0; k0 < IN; k0 += 16)
        gemm16(Asm, W01, W23, tj, tb, k0, acc);
}

// H phase: own-span GEMM, then 15 peer slices pipelined (poll+LDG prefetch
// under GEMM), then pointwise; hn -> global (next parity) + own smem span.
__device__ __forceinline__ void cell_h(int d, int b0, int j0, int own,
                                       const float* __restrict__ hsrc,
                                       float* __restrict__ hdst,
                                       const float* W01, const float* W23,
                                       float* Asm, u64 acc[4][2],
                                       float c_reg[4], int wid, int lane,
                                       int tj, int tb, int round, int gbase) {
    // own slice was staged into Asm at previous pointwise (or init)
    gemm16(Asm, W01, W23, tj, tb, IN + own * 16, acc);

    const int row_l = lane >> 2;                 // 0..7
    const int f4l = lane & 3;                    // 0..3
    const float* hrow = hsrc + (size_t)((d << 7) + b0 + 8 * wid + row_l) * HID + f4l * 4;
    float* arow = Asm + (8 * wid + row_l) * AS + IN + f4l * 4;

    int q = (own + 1) & 15;
    pollflag(gbase + q, round);
    float4 v = *(const float4*)(hrow + q * 16);

#pragma unroll 1
    for (int i = 0; i < 15; i++) {
        int qc = q;
        *(float4*)(arow + qc * 16) = v;
        __syncwarp();
        if (i < 14) {
            q = (own + 2 + i) & 15;
            pollflag(gbase + q, round);
            v = *(const float4*)(hrow + q * 16);
        }
        gemm16(Asm, W01, W23, tj, tb, IN + qc * 16, acc);
    }

    int j = j0 + tj;
    int ownc = IN + own * 16 + tj;
#pragma unroll
    for (int bi = 0; bi < 4; bi++) {
        int row = tb * 4 + bi;
        float gi, gf, gg, go;
        unpack2(gi, gf, acc[bi][0]);
        unpack2(gg, go, acc[bi][1]);
        float cn = fsig(gf) * c_reg[bi] + fsig(gi) * ftanh(gg);
        float hn = fsig(go) * ftanh(cn);
        c_reg[bi] = cn;
        hdst[(size_t)((d << 7) + b0 + row) * HID + j] = hn;
        Asm[row * AS + ownc] = hn;               // own slice for next round
    }
}

__global__ void __launch_bounds__(NTHR, 1)
lstm_s2s_kernel(const float* __restrict__ x,
                const float* __restrict__ eWih, const float* __restrict__ eWhh,
                const float* __restrict__ ebih, const float* __restrict__ ebhh,
                const float* __restrict__ dWih, const float* __restrict__ dWhh,
                const float* __restrict__ dbih, const float* __restrict__ dbhh,
                const float* __restrict__ linW, const float* __restrict__ linb,
                float* __restrict__ out) {
    extern __shared__ float smem[];
    float* W01  = smem;                       // [320][34]
    float* W23  = W01 + KTOT * WS2;           // [320][34]
    float* Asm  = W23 + KTOT * WS2;           // [32][328]
    float* bsum = Asm + 32 * AS;              // [64]

    const int ct = blockIdx.x;
    const int d = ct >> 6;
    const int rem = ct & 63;
    const int b0 = (rem >> 4) * 32;
    const int own = rem & 15;                 // this CTA's j-tile
    const int j0 = own * 16;
    const int gbase = ct & ~15;               // 16 CTAs sharing (dir, b-tile)
    const int tid = threadIdx.x;
    const int wid = tid >> 5;
    const int lane = tid & 31;
    const int tj = tid & 15;
    const int tb = tid >> 4;

    float c_reg[4] = {0.f, 0.f, 0.f, 0.f};
    u64 acc[4][2];
    int hr = 0;

    // fresh state: zero own h slice in buffer 0 + own smem span
    for (int idx = tid; idx < 32 * 16; idx += NTHR) {
        int bb = idx >> 4, jj = idx & 15;
        g_h[0][(size_t)((d << 7) + b0 + bb) * HID + j0 + jj] = 0.f;
    }
#pragma unroll
    for (int bi = 0; bi < 4; bi++)
        Asm[(tb * 4 + bi) * AS + IN + own * 16 + tj] = 0.f;
    release(1);
    int round = 1;

    load_phase_weights(W01, W23, bsum, eWih, eWhh, ebih, ebhh, d, j0);
    __syncthreads();

    // ===== encoder =====
    for (int r = 0; r < SEQLEN; r++) {
        int t = (d == 0) ? r : (SEQLEN - 1 - r);
        cell_pre(x + t * IN, SEQLEN * IN, b0, W01, W23, Asm, bsum, acc,
                 wid, lane, tj, tb);
        cell_h(d, b0, j0, own, g_h[hr & 1], g_h[(hr + 1) & 1],
               W01, W23, Asm, acc, c_reg, wid, lane, tj, tb, round, gbase);
        hr++;
        release(round + 1); round++;
    }

    // ===== switch to decoder weights =====
    load_phase_weights(W01, W23, bsum, dWih, dWhh, dbih, dbhh, d, j0);
    __syncthreads();

    // ===== decoder =====
    for (int t = 0; t < PRED; t++) {
        int L = (t == 0) ? 1 : t;
        for (int s = 0; s < L; s++) {
            const float* src;
            int stride;
            if (t == 0) {
                src = x + (SEQLEN - 1) * IN;      // x[:, -1, :]
                stride = SEQLEN * IN;
            } else {
                int yi = (d == 0) ? s : (L - 1 - s);
                src = g_y + (size_t)yi * BATCH * IN;
                stride = IN;
            }
            cell_pre(src, stride, b0, W01, W23, Asm, bsum, acc,
                     wid, lane, tj, tb);
            cell_h(d, b0, j0, own, g_h[hr & 1], g_h[(hr + 1) & 1],
                   W01, W23, Asm, acc, c_reg, wid, lane, tj, tb, round, gbase);
            hr++;
            release(round + 1); round++;
        }

        // ---- projection (CTAs 0..63): y = concat(hF,hB) @ linW^T + linb
        if (ct < 64) {
            if (tid < 32) {                       // producers of this b-tile
                int base = (ct >> 4) * 16;
                int idx = base + (tid & 15) + ((tid & 16) ? 64 : 0);
                pollflag(idx, round);
            }
            __syncthreads();
            const float* hb = g_h[hr & 1];
            int b = (ct << 1) + (tid >> 6);       // 2 batch rows per CTA
            int col = tid & 63;
            const float4* w4 = (const float4*)(linW + col * (2 * HID));
            const float4* h0 = (const float4*)(hb + (size_t)b * HID);
            const float4* h1 = (const float4*)(hb + (size_t)(BATCH + b) * HID);
            float s = linb[col];
#pragma unroll 8
            for (int q = 0; q < HID / 4; q++) {
                float4 f = __ldcg(h0 + q);
                float4 w = __ldg(w4 + q);
                s += f.x * w.x + f.y * w.y + f.z * w.z + f.w * w.w;
            }
#pragma unroll 8
            for (int q = 0; q < HID / 4; q++) {
                float4 f = __ldcg(h1 + q);
                float4 w = __ldg(w4 + HID / 4 + q);
                s += f.x * w.x + f.y * w.y + f.z * w.z + f.w * w.w;
            }
            g_y[((size_t)t * BATCH + b) * IN + col] = s;
            out[((size_t)b * PRED + t) * IN + col] = s;
        }
        release(round + 1); round++;
        // g_y rows for this b-tile come from projection CTAs [b0/2, b0/2+16)
        waitf(b0 >> 1, 16, round);
    }
}

extern "C" void kernel_launch(void* const* d_in, const int* in_sizes, int n_in,
                              void* d_out, int out_size) {
    const float* x    = (const float*)d_in[0];
    const float* eWih = (const float*)d_in[1];
    const float* eWhh = (const float*)d_in[2];
    const float* ebih = (const float*)d_in[3];
    const float* ebhh = (const float*)d_in[4];
    const float* dWih = (const float*)d_in[5];
    const float* dWhh = (const float*)d_in[6];
    const float* dbih = (const float*)d_in[7];
    const float* dbhh = (const float*)d_in[8];
    const float* linW = (const float*)d_in[9];
    const float* linb = (const float*)d_in[10];
    float* out = (float*)d_out;

    void* flagsPtr = nullptr;
    cudaGetSymbolAddress(&flagsPtr, g_flags);
    cudaMemsetAsync(flagsPtr, 0, sizeof(int) * NBLK, 0);

    cudaFuncSetAttribute(lstm_s2s_kernel,
                         cudaFuncAttributeMaxDynamicSharedMemorySize, SMEM_BYTES);

    lstm_s2s_kernel<<<NBLK, NTHR, SMEM_BYTES>>>(
        x, eWih, eWhh, ebih, ebhh, dWih, dWhh, dbih, dbhh, linW, linb, out);
}

// round 13
// speedup vs baseline: 1.3709x; 1.3709x over previous
#include <cuda_runtime.h>
#include <cstdint>

// ---------------------------------------------------------------------------
// Seq2seq BiLSTM (encoder 336 + autoregressive decoder 24), persistent kernel.
//
// Grid = 128 CTAs = 2 dirs x 4 batch-tiles(32) x 16 j-tiles(16), 128 thr/CTA.
// Thread owns 4 batch rows x 4 gates of one hidden unit (f32x2 gate pairs).
// Per-warp row ownership (warp w = batch rows 8w..8w+8): all staging syncs are
// __syncwarp; one __syncthreads per round (at flag release).
// Latency-slotted round: x-GEMM k0..32 before the wait; h LDG batches issued
// under x-GEMM k32..64 and the first h-GEMM chunk. g_h double-buffered.
// ---------------------------------------------------------------------------

#define NBLK 128
#define NTHR 128

namespace {
constexpr int BATCH = 128;
constexpr int SEQLEN = 336;
constexpr int PRED = 24;
constexpr int IN = 64;
constexpr int HID = 256;
constexpr int KTOT = IN + HID;          // 320
constexpr int WS = 68;                  // W smem row stride (floats)
constexpr int AS = 328;                 // A smem row stride (floats)
constexpr int SMEM_FLOATS = KTOT * WS + 32 * AS + 64;
constexpr int SMEM_BYTES = SMEM_FLOATS * 4;   // 129280 B
}

__device__ float g_h[2][2 * BATCH * HID];       // [parity][dir*BATCH+b][HID]
__device__ float g_y[PRED * BATCH * IN];
__device__ int   g_flags[NBLK];

using u64 = unsigned long long;

__device__ __forceinline__ int ld_acq(const int* p) {
    int v;
    asm volatile("ld.global.acquire.gpu.b32 %0, [%1];" : "=r"(v) : "l"(p) : "memory");
    return v;
}
__device__ __forceinline__ void st_rel(int* p, int v) {
    asm volatile("st.global.release.gpu.b32 [%0], %1;" :: "l"(p), "r"(v) : "memory");
}
__device__ __forceinline__ u64 ffma2(u64 a, u64 b, u64 c) {
    u64 d;
    asm("fma.rn.f32x2 %0, %1, %2, %3;" : "=l"(d) : "l"(a), "l"(b), "l"(c));
    return d;
}
__device__ __forceinline__ u64 pack2(float lo, float hi) {
    u64 d;
    asm("mov.b64 %0, {%1, %2};" : "=l"(d) : "f"(lo), "f"(hi));
    return d;
}
__device__ __forceinline__ void unpack2(float& lo, float& hi, u64 v) {
    asm("mov.b64 {%0, %1}, %2;" : "=f"(lo), "=f"(hi) : "l"(v));
}
__device__ __forceinline__ float fsig(float x) {
    return __fdividef(1.0f, 1.0f + __expf(-x));
}
__device__ __forceinline__ float ftanh(float x) {
    float ax = fabsf(x);
    float t = __expf(-2.0f * ax);
    float r = __fdividef(1.0f - t, 1.0f + t);
    return copysignf(r, x);
}

__device__ __forceinline__ void release(int v) {
    __syncthreads();
    if (threadIdx.x == 0) st_rel(&g_flags[blockIdx.x], v);
}
__device__ __forceinline__ void waitf(int base, int cnt, int v) {
    if (threadIdx.x < cnt) {
        const int* p = &g_flags[base + threadIdx.x];
        while (ld_acq(p) < v) { }
    }
    __syncthreads();
}
__device__ __forceinline__ void pollflag(int idx, int v) {
    const int* p = &g_flags[idx];
    while (ld_acq(p) < v) { }
}

// W slice -> SMEM: Wsm[k*WS + jj*4 + g], source row = g*256 + j0 + jj.
__device__ void load_phase_weights(float* Wsm, float* bsum,
                                   const float* __restrict__ Wih,
                                   const float* __restrict__ Whh,
                                   const float* __restrict__ bih,
                                   const float* __restrict__ bhh,
                                   int d, int j0) {
    for (int idx = threadIdx.x; idx < 64 * KTOT; idx += NTHR) {
        int c = idx / KTOT;
        int k = idx - c * KTOT;
        int jj = c >> 2, g = c & 3;
        int row = g * 256 + j0 + jj;
        float v = (k < IN) ? Wih[(d * 1024 + row) * IN + k]
                           : Whh[(d * 1024 + row) * HID + (k - IN)];
        Wsm[k * WS + c] = v;
    }
    for (int c = threadIdx.x; c < 64; c += NTHR) {
        int jj = c >> 2, g = c & 3;
        int row = g * 256 + j0 + jj;
        bsum[c] = bih[d * 1024 + row] + bhh[d * 1024 + row];
    }
}

// Packed f32x2 GEMM over k range [k0,k1).
__device__ __forceinline__ void gemm_span(const float* Asm, const float* Wsm,
                                          int tj, int tb, int k0, int k1,
                                          u64 acc[4][2]) {
    const float* A0 = Asm + (tb * 4) * AS;
#pragma unroll 4
    for (int k = k0; k < k1; k += 4) {
        float4 a0 = *(const float4*)(A0 + k);
        float4 a1 = *(const float4*)(A0 + AS + k);
        float4 a2 = *(const float4*)(A0 + 2 * AS + k);
        float4 a3 = *(const float4*)(A0 + 3 * AS + k);
        float av[4][4] = {{a0.x, a0.y, a0.z, a0.w},
                          {a1.x, a1.y, a1.z, a1.w},
                          {a2.x, a2.y, a2.z, a2.w},
                          {a3.x, a3.y, a3.z, a3.w}};
#pragma unroll
        for (int kk = 0; kk < 4; kk++) {
            const u64* Wq = (const u64*)(Wsm + (k + kk) * WS) + tj * 2;
            u64 w01 = Wq[0];
            u64 w23 = Wq[1];
#pragma unroll
            for (int bi = 0; bi < 4; bi++) {
                u64 ad = pack2(av[bi][kk], av[bi][kk]);
                acc[bi][0] = ffma2(ad, w01, acc[bi][0]);
                acc[bi][1] = ffma2(ad, w23, acc[bi][1]);
            }
        }
    }
}

// One full LSTM step with latency-slotted scheduling (per-warp rows).
__device__ __forceinline__ void cell_step(const float* __restrict__ src,
                                          int rowStride, int d, int b0, int j0,
                                          const float* __restrict__ hsrc,
                                          float* __restrict__ hdst,
                                          const float* Wsm, float* Asm,
                                          const float* bsum, float c_reg[4],
                                          int round, int gbase,
                                          int wid, int lane, int tj, int tb) {
    // ---- stage x rows [8w, 8w+8), cols 0..63 (per-warp)
#pragma unroll
    for (int it = 0; it < 4; it++) {
        int idx = lane + 32 * it;                  // 0..127
        int row = 8 * wid + (idx >> 4);
        int f4 = idx & 15;
        float4 v = __ldcg((const float4*)(src + (size_t)(b0 + row) * rowStride) + f4);
        *(float4*)(Asm + row * AS + f4 * 4) = v;
    }
    __syncwarp();

    u64 acc[4][2];
    {
        float4 bv = *(const float4*)(bsum + tj * 4);
        u64 b01 = pack2(bv.x, bv.y);
        u64 b23 = pack2(bv.z, bv.w);
#pragma unroll
        for (int bi = 0; bi < 4; bi++) { acc[bi][0] = b01; acc[bi][1] = b23; }
    }

    // x-GEMM first half before the wait (covers release->visibility latency)
    gemm_span(Asm, Wsm, tj, tb, 0, 32, acc);

    // ---- warp-local wait on the 16 group flags
    if (lane < 16) pollflag(gbase + lane, round);
    __syncwarp();

    const size_t hbase = (size_t)((d << 7) + b0 + 8 * wid) * HID;

    // issue h LDG batch A (8 rows x 1 float4/lane, h cols 4*lane..4*lane+4)
    float4 va[8];
#pragma unroll
    for (int u = 0; u < 8; u++)
        va[u] = __ldcg((const float4*)(hsrc + hbase + (size_t)u * HID) + lane);

    // x-GEMM second half under LDG-A latency
    gemm_span(Asm, Wsm, tj, tb, 32, IN, acc);

#pragma unroll
    for (int u = 0; u < 8; u++)
        *(float4*)(Asm + (8 * wid + u) * AS + IN + lane * 4) = va[u];

    // issue h LDG batch B (h cols 128..256)
    float4 vb[8];
#pragma unroll
    for (int u = 0; u < 8; u++)
        vb[u] = __ldcg((const float4*)(hsrc + hbase + (size_t)u * HID) + 32 + lane);

    __syncwarp();
    // h-GEMM first 128 cols under LDG-B latency
    gemm_span(Asm, Wsm, tj, tb, IN, IN + 128, acc);

#pragma unroll
    for (int u = 0; u < 8; u++)
        *(float4*)(Asm + (8 * wid + u) * AS + IN + 128 + lane * 4) = vb[u];
    __syncwarp();

    gemm_span(Asm, Wsm, tj, tb, IN + 128, KTOT, acc);

    // ---- pointwise; h -> next-parity buffer
    int j = j0 + tj;
#pragma unroll
    for (int bi = 0; bi < 4; bi++) {
        int row = tb * 4 + bi;
        float gi, gf, gg, go;
        unpack2(gi, gf, acc[bi][0]);
        unpack2(gg, go, acc[bi][1]);
        float cn = fsig(gf) * c_reg[bi] + fsig(gi) * ftanh(gg);
        float hn = fsig(go) * ftanh(cn);
        c_reg[bi] = cn;
        hdst[(size_t)((d << 7) + b0 + row) * HID + j] = hn;
    }
}

__global__ void __launch_bounds__(NTHR, 1)
lstm_s2s_kernel(const float* __restrict__ x,
                const float* __restrict__ eWih, const float* __restrict__ eWhh,
                const float* __restrict__ ebih, const float* __restrict__ ebhh,
                const float* __restrict__ dWih, const float* __restrict__ dWhh,
                const float* __restrict__ dbih, const float* __restrict__ dbhh,
                const float* __restrict__ linW, const float* __restrict__ linb,
                float* __restrict__ out) {
    extern __shared__ float smem[];
    float* Wsm  = smem;                       // [320][68]
    float* Asm  = Wsm + KTOT * WS;            // [32][328]
    float* bsum = Asm + 32 * AS;              // [64]

    const int ct = blockIdx.x;
    const int d = ct >> 6;
    const int rem = ct & 63;
    const int b0 = (rem >> 4) * 32;
    const int j0 = (rem & 15) * 16;
    const int gbase = ct & ~15;               // 16 CTAs sharing (dir, b-tile)
    const int tid = threadIdx.x;
    const int wid = tid >> 5;
    const int lane = tid & 31;
    const int tj = tid & 15;
    const int tb = tid >> 4;

    float c_reg[4] = {0.f, 0.f, 0.f, 0.f};
    int hr = 0;

    // fresh state every replay: zero own h slice in buffer 0
    for (int idx = tid; idx < 32 * 16; idx += NTHR) {
        int bb = idx >> 4, jj = idx & 15;
        g_h[0][(size_t)((d << 7) + b0 + bb) * HID + j0 + jj] = 0.f;
    }
    release(1);
    int round = 1;

    load_phase_weights(Wsm, bsum, eWih, eWhh, ebih, ebhh, d, j0);
    __syncthreads();

    // ===== encoder =====
    for (int r = 0; r < SEQLEN; r++) {
        int t = (d == 0) ? r : (SEQLEN - 1 - r);
        cell_step(x + t * IN, SEQLEN * IN, d, b0, j0,
                  g_h[hr & 1], g_h[(hr + 1) & 1],
                  Wsm, Asm, bsum, c_reg, round, gbase, wid, lane, tj, tb);
        hr++;
        release(round + 1); round++;
    }

    // ===== switch to decoder weights =====
    load_phase_weights(Wsm, bsum, dWih, dWhh, dbih, dbhh, d, j0);
    __syncthreads();

    // ===== decoder: 24 autoregressive iterations =====
    for (int t = 0; t < PRED; t++) {
        int L = (t == 0) ? 1 : t;
        for (int s = 0; s < L; s++) {
            const float* src;
            int stride;
            if (t == 0) {
                src = x + (SEQLEN - 1) * IN;      // x[:, -1, :]
                stride = SEQLEN * IN;
            } else {
                int yi = (d == 0) ? s : (L - 1 - s);
                src = g_y + (size_t)yi * BATCH * IN;
                stride = IN;
            }
            cell_step(src, stride, d, b0, j0,
                      g_h[hr & 1], g_h[(hr + 1) & 1],
                      Wsm, Asm, bsum, c_reg, round, gbase, wid, lane, tj, tb);
            hr++;
            release(round + 1); round++;
        }

        // ---- projection (CTAs 0..63): y = concat(hF,hB) @ linW^T + linb
        if (ct < 64) {
            if (tid < 32) {                        // producers of this b-tile
                int base = (ct >> 4) * 16;
                pollflag(base + (tid & 15) + ((tid & 16) ? 64 : 0), round);
            }
            __syncthreads();
            const float* hb = g_h[hr & 1];
            int b = (ct << 1) + (tid >> 6);        // 2 batch rows per CTA
            int col = tid & 63;
            const float4* w4 = (const float4*)(linW + col * (2 * HID));
            const float4* h0 = (const float4*)(hb + (size_t)b * HID);
            const float4* h1 = (const float4*)(hb + (size_t)(BATCH + b) * HID);
            float s = linb[col];
#pragma unroll 8
            for (int q = 0; q < HID / 4; q++) {
                float4 f = __ldcg(h0 + q);
                float4 w = __ldg(w4 + q);
                s += f.x * w.x + f.y * w.y + f.z * w.z + f.w * w.w;
            }
#pragma unroll 8
            for (int q = 0; q < HID / 4; q++) {
                float4 f = __ldcg(h1 + q);
                float4 w = __ldg(w4 + HID / 4 + q);
                s += f.x * w.x + f.y * w.y + f.z * w.z + f.w * w.w;
            }
            g_y[((size_t)t * BATCH + b) * IN + col] = s;
            out[((size_t)b * PRED + t) * IN + col] = s;
        }
        release(round + 1); round++;
        // g_y rows for this b-tile come from projection CTAs [b0/2, b0/2+16)
        waitf(b0 >> 1, 16, round);
    }
}

extern "C" void kernel_launch(void* const* d_in, const int* in_sizes, int n_in,
                              void* d_out, int out_size) {
    const float* x    = (const float*)d_in[0];
    const float* eWih = (const float*)d_in[1];
    const float* eWhh = (const float*)d_in[2];
    const float* ebih = (const float*)d_in[3];
    const float* ebhh = (const float*)d_in[4];
    const float* dWih = (const float*)d_in[5];
    const float* dWhh = (const float*)d_in[6];
    const float* dbih = (const float*)d_in[7];
    const float* dbhh = (const float*)d_in[8];
    const float* linW = (const float*)d_in[9];
    const float* linb = (const float*)d_in[10];
    float* out = (float*)d_out;

    void* flagsPtr = nullptr;
    cudaGetSymbolAddress(&flagsPtr, g_flags);
    cudaMemsetAsync(flagsPtr, 0, sizeof(int) * NBLK, 0);

    cudaFuncSetAttribute(lstm_s2s_kernel,
                         cudaFuncAttributeMaxDynamicSharedMemorySize, SMEM_BYTES);

    lstm_s2s_kernel<<<NBLK, NTHR, SMEM_BYTES>>>(
        x, eWih, eWhh, ebih, ebhh, dWih, dWhh, dbih, dbhh, linW, linb, out);
}

// round 14
// speedup vs baseline: 1.9055x; 1.3900x over previous
#include <cuda_runtime.h>
#include <cstdint>

// ---------------------------------------------------------------------------
// Seq2seq BiLSTM (encoder 336 + autoregressive decoder 24), persistent kernel.
//
// Grid = 128 CTAs = 2 dirs x 4 batch-tiles(32) x 16 j-tiles(16), 256 thr/CTA.
// SPLIT-K: warps 0-3 (half 0) handle k in [0,64)u[64,192); warps 4-7 (half 1)
// handle k in [32..64 pre] ... precisely: pre-wait x-GEMM half0 k0..32,
// half1 k32..64; post-wait h-GEMM half0 k64..192, half1 k192..320.
// Each thread: 4 batch rows x 4 gates of one hidden unit (f32x2 gate pairs)
// over its K half; partials reduced through smem (stride-9 u64, 2-way max).
// Per-SMSP co-residency: one half0 + one half1 warp -> LDS stalls overlap,
// total LDS traffic identical to the 128-thread kernel.
// g_h double-buffered by parity; release/acquire flag barrier (16-CTA groups).
// ---------------------------------------------------------------------------

#define NBLK 128
#define NTHR 256

namespace {
constexpr int BATCH = 128;
constexpr int SEQLEN = 336;
constexpr int PRED = 24;
constexpr int IN = 64;
constexpr int HID = 256;
constexpr int KTOT = IN + HID;          // 320
constexpr int WS = 68;                  // W smem row stride (floats)
constexpr int AS = 328;                 // A smem row stride (floats)
constexpr int RED_U64 = 128 * 9;        // padded partial-acc scratch
constexpr int SMEM_FLOATS = KTOT * WS + 32 * AS + 64 + RED_U64 * 2;
constexpr int SMEM_BYTES = SMEM_FLOATS * 4;   // 138496 B
}

__device__ float g_h[2][2 * BATCH * HID];       // [parity][dir*BATCH+b][HID]
__device__ float g_y[PRED * BATCH * IN];
__device__ int   g_flags[NBLK];

using u64 = unsigned long long;

__device__ __forceinline__ int ld_acq(const int* p) {
    int v;
    asm volatile("ld.global.acquire.gpu.b32 %0, [%1];" : "=r"(v) : "l"(p) : "memory");
    return v;
}
__device__ __forceinline__ void st_rel(int* p, int v) {
    asm volatile("st.global.release.gpu.b32 [%0], %1;" :: "l"(p), "r"(v) : "memory");
}
__device__ __forceinline__ u64 ffma2(u64 a, u64 b, u64 c) {
    u64 d;
    asm("fma.rn.f32x2 %0, %1, %2, %3;" : "=l"(d) : "l"(a), "l"(b), "l"(c));
    return d;
}
__device__ __forceinline__ u64 fadd2(u64 a, u64 b) {
    u64 d;
    asm("add.rn.f32x2 %0, %1, %2;" : "=l"(d) : "l"(a), "l"(b));
    return d;
}
__device__ __forceinline__ u64 pack2(float lo, float hi) {
    u64 d;
    asm("mov.b64 %0, {%1, %2};" : "=l"(d) : "f"(lo), "f"(hi));
    return d;
}
__device__ __forceinline__ void unpack2(float& lo, float& hi, u64 v) {
    asm("mov.b64 {%0, %1}, %2;" : "=f"(lo), "=f"(hi) : "l"(v));
}
__device__ __forceinline__ float fsig(float x) {
    return __fdividef(1.0f, 1.0f + __expf(-x));
}
__device__ __forceinline__ float ftanh(float x) {
    float ax = fabsf(x);
    float t = __expf(-2.0f * ax);
    float r = __fdividef(1.0f - t, 1.0f + t);
    return copysignf(r, x);
}

__device__ __forceinline__ void release(int v) {
    __syncthreads();
    if (threadIdx.x == 0) st_rel(&g_flags[blockIdx.x], v);
}
__device__ __forceinline__ void waitf(int base, int cnt, int v) {
    if (threadIdx.x < cnt) {
        const int* p = &g_flags[base + threadIdx.x];
        while (ld_acq(p) < v) { }
    }
    __syncthreads();
}
__device__ __forceinline__ void pollflag(int idx, int v) {
    const int* p = &g_flags[idx];
    while (ld_acq(p) < v) { }
}

// W slice -> SMEM: Wsm[k*WS + jj*4 + g], source row = g*256 + j0 + jj.
__device__ void load_phase_weights(float* Wsm, float* bsum,
                                   const float* __restrict__ Wih,
                                   const float* __restrict__ Whh,
                                   const float* __restrict__ bih,
                                   const float* __restrict__ bhh,
                                   int d, int j0) {
    for (int idx = threadIdx.x; idx < 64 * KTOT; idx += NTHR) {
        int c = idx / KTOT;
        int k = idx - c * KTOT;
        int jj = c >> 2, g = c & 3;
        int row = g * 256 + j0 + jj;
        float v = (k < IN) ? Wih[(d * 1024 + row) * IN + k]
                           : Whh[(d * 1024 + row) * HID + (k - IN)];
        Wsm[k * WS + c] = v;
    }
    for (int c = threadIdx.x; c < 64; c += NTHR) {
        int jj = c >> 2, g = c & 3;
        int row = g * 256 + j0 + jj;
        bsum[c] = bih[d * 1024 + row] + bhh[d * 1024 + row];
    }
}

// Packed f32x2 GEMM over k range [k0,k1); 4 rows x (i,f),(g,o) pairs.
__device__ __forceinline__ void gemm_span(const float* Asm, const float* Wsm,
                                          int tj, int tb, int k0, int k1,
                                          u64 acc[4][2]) {
    const float* A0 = Asm + (tb * 4) * AS;
#pragma unroll 4
    for (int k = k0; k < k1; k += 4) {
        float4 a0 = *(const float4*)(A0 + k);
        float4 a1 = *(const float4*)(A0 + AS + k);
        float4 a2 = *(const float4*)(A0 + 2 * AS + k);
        float4 a3 = *(const float4*)(A0 + 3 * AS + k);
        float av[4][4] = {{a0.x, a0.y, a0.z, a0.w},
                          {a1.x, a1.y, a1.z, a1.w},
                          {a2.x, a2.y, a2.z, a2.w},
                          {a3.x, a3.y, a3.z, a3.w}};
#pragma unroll
        for (int kk = 0; kk < 4; kk++) {
            const u64* Wq = (const u64*)(Wsm + (k + kk) * WS) + tj * 2;
            u64 w01 = Wq[0];
            u64 w23 = Wq[1];
#pragma unroll
            for (int bi = 0; bi < 4; bi++) {
                u64 ad = pack2(av[bi][kk], av[bi][kk]);
                acc[bi][0] = ffma2(ad, w01, acc[bi][0]);
                acc[bi][1] = ffma2(ad, w23, acc[bi][1]);
            }
        }
    }
}

// One LSTM step, split-K across the two thread halves.
__device__ __forceinline__ void cell_step(const float* __restrict__ src,
                                          int rowStride, int d, int b0, int j0,
                                          const float* __restrict__ hsrc,
                                          float* __restrict__ hdst,
                                          const float* Wsm, float* Asm,
                                          u64* redsm, const float* bsum,
                                          float c_reg[4], int round, int gbase,
                                          int tid, int hg, int tj, int tb) {
    // ---- 1. stage x tile (32 rows x 16 float4): threads 0..127, 1 each
    if (tid < 128) {
        int row = tid >> 2;
        int f4 = tid & 3;
        // 4 float4 per row? no: 16 f4/row, 32 rows = 512 f4. redo:
    }
    // 512 float4, 2 per thread
#pragma unroll
    for (int it = 0; it < 2; it++) {
        int idx = tid + it * NTHR;                 // 0..511
        int row = idx >> 4;
        int f4 = idx & 15;
        float4 v = __ldcg((const float4*)(src + (size_t)(b0 + row) * rowStride) + f4);
        *(float4*)(Asm + row * AS + f4 * 4) = v;
    }
    __syncthreads();

    // ---- 2. acc init + pre-wait x-GEMM (half0: k 0..32, half1: k 32..64)
    u64 acc[4][2];
    if (hg == 0) {
        float4 bv = *(const float4*)(bsum + tj * 4);
        u64 b01 = pack2(bv.x, bv.y);
        u64 b23 = pack2(bv.z, bv.w);
#pragma unroll
        for (int bi = 0; bi < 4; bi++) { acc[bi][0] = b01; acc[bi][1] = b23; }
    } else {
#pragma unroll
        for (int bi = 0; bi < 4; bi++) { acc[bi][0] = 0ull; acc[bi][1] = 0ull; }
    }
    if (hg == 0) gemm_span(Asm, Wsm, tj, tb, 0, 32, acc);
    else         gemm_span(Asm, Wsm, tj, tb, 32, IN, acc);

    // ---- 3. wait on the 16 group flags
    if (tid < 16) pollflag(gbase + tid, round);
    __syncthreads();

    // ---- 4. stage h tile (32 rows x 64 float4 = 2048 f4), 8 per thread
    float4 v[8];
#pragma unroll
    for (int u = 0; u < 8; u++) {
        int idx = tid + u * NTHR;
        int row = idx >> 6;
        int slot = idx & 63;
        v[u] = __ldcg((const float4*)(hsrc + (size_t)((d << 7) + b0 + row) * HID) + slot);
    }
#pragma unroll
    for (int u = 0; u < 8; u++) {
        int idx = tid + u * NTHR;
        int row = idx >> 6;
        int slot = idx & 63;
        *(float4*)(Asm + row * AS + IN + slot * 4) = v[u];
    }
    __syncthreads();

    // ---- 5. h-GEMM (half0: k 64..192, half1: k 192..320)
    if (hg == 0) gemm_span(Asm, Wsm, tj, tb, IN, IN + 128, acc);
    else         gemm_span(Asm, Wsm, tj, tb, IN + 128, KTOT, acc);

    // ---- 6. cross-half reduction (stride-9 u64 scratch, 2-way max conflict)
    if (hg == 1) {
        u64* r = redsm + (size_t)(tid & 127) * 9;
#pragma unroll
        for (int bi = 0; bi < 4; bi++) {
            r[bi * 2 + 0] = acc[bi][0];
            r[bi * 2 + 1] = acc[bi][1];
        }
    }
    __syncthreads();

    if (hg == 0) {
        const u64* r = redsm + (size_t)tid * 9;
        int j = j0 + tj;
#pragma unroll
        for (int bi = 0; bi < 4; bi++) {
            u64 s01 = fadd2(acc[bi][0], r[bi * 2 + 0]);
            u64 s23 = fadd2(acc[bi][1], r[bi * 2 + 1]);
            float gi, gf, gg, go;
            unpack2(gi, gf, s01);
            unpack2(gg, go, s23);
            float cn = fsig(gf) * c_reg[bi] + fsig(gi) * ftanh(gg);
            float hn = fsig(go) * ftanh(cn);
            c_reg[bi] = cn;
            hdst[(size_t)((d << 7) + b0 + tb * 4 + bi) * HID + j] = hn;
        }
    }
}

__global__ void __launch_bounds__(NTHR, 1)
lstm_s2s_kernel(const float* __restrict__ x,
                const float* __restrict__ eWih, const float* __restrict__ eWhh,
                const float* __restrict__ ebih, const float* __restrict__ ebhh,
                const float* __restrict__ dWih, const float* __restrict__ dWhh,
                const float* __restrict__ dbih, const float* __restrict__ dbhh,
                const float* __restrict__ linW, const float* __restrict__ linb,
                float* __restrict__ out) {
    extern __shared__ float smem[];
    float* Wsm  = smem;                        // [320][68]
    float* Asm  = Wsm + KTOT * WS;             // [32][328]
    float* bsum = Asm + 32 * AS;               // [64]
    u64*   redsm = (u64*)(bsum + 64);          // [128][9] u64
    float* redf = (float*)redsm;               // projection scratch

    const int ct = blockIdx.x;
    const int d = ct >> 6;
    const int rem = ct & 63;
    const int b0 = (rem >> 4) * 32;
    const int j0 = (rem & 15) * 16;
    const int gbase = ct & ~15;                // 16 CTAs sharing (dir, b-tile)
    const int tid = threadIdx.x;
    const int hg = tid >> 7;                   // K-half: warps 0-3 / 4-7
    const int tid7 = tid & 127;
    const int tj = tid7 & 15;
    const int tb = tid7 >> 4;                  // 0..7, 4 rows each

    float c_reg[4] = {0.f, 0.f, 0.f, 0.f};
    int hr = 0;

    // fresh state every replay: zero own h slice in buffer 0
    for (int idx = tid; idx < 32 * 16; idx += NTHR) {
        int bb = idx >> 4, jj = idx & 15;
        g_h[0][(size_t)((d << 7) + b0 + bb) * HID + j0 + jj] = 0.f;
    }
    release(1);
    int round = 1;

    load_phase_weights(Wsm, bsum, eWih, eWhh, ebih, ebhh, d, j0);
    __syncthreads();

    // ===== encoder =====
    for (int r = 0; r < SEQLEN; r++) {
        int t = (d == 0) ? r : (SEQLEN - 1 - r);
        cell_step(x + t * IN, SEQLEN * IN, d, b0, j0,
                  g_h[hr & 1], g_h[(hr + 1) & 1],
                  Wsm, Asm, redsm, bsum, c_reg, round, gbase, tid, hg, tj, tb);
        hr++;
        release(round + 1); round++;
    }

    // ===== switch to decoder weights =====
    load_phase_weights(Wsm, bsum, dWih, dWhh, dbih, dbhh, d, j0);
    __syncthreads();

    // ===== decoder: 24 autoregressive iterations =====
    for (int t = 0; t < PRED; t++) {
        int L = (t == 0) ? 1 : t;
        for (int s = 0; s < L; s++) {
            const float* src;
            int stride;
            if (t == 0) {
                src = x + (SEQLEN - 1) * IN;       // x[:, -1, :]
                stride = SEQLEN * IN;
            } else {
                int yi = (d == 0) ? s : (L - 1 - s);
                src = g_y + (size_t)yi * BATCH * IN;
                stride = IN;
            }
            cell_step(src, stride, d, b0, j0,
                      g_h[hr & 1], g_h[(hr + 1) & 1],
                      Wsm, Asm, redsm, bsum, c_reg, round, gbase, tid, hg, tj, tb);
            hr++;
            release(round + 1); round++;
        }

        // ---- projection (CTAs 0..63): y = concat(hF,hB) @ linW^T + linb
        if (ct < 64) {
            if (tid < 32) {                        // producers of this b-tile
                int base = (ct >> 4) * 16;
                pollflag(base + (tid & 15) + ((tid & 16) ? 64 : 0), round);
            }
            __syncthreads();
            const float* hb = g_h[hr & 1];
            int bsel = tid >> 7;                   // 0..1
            int half = (tid >> 6) & 1;             // 0 = fwd h, 1 = bwd h
            int col  = tid & 63;
            int b = (ct << 1) + bsel;
            const float4* w4 = (const float4*)(linW + col * (2 * HID)) + half * (HID / 4);
            const float4* hv = (const float4*)(hb + (size_t)(half * BATCH + b) * HID);
            float s = 0.f;
#pragma unroll 8
            for (int q = 0; q < HID / 4; q++) {
                float4 f = __ldcg(hv + q);
                float4 w = __ldg(w4 + q);
                s += f.x * w.x + f.y * w.y + f.z * w.z + f.w * w.w;
            }
            redf[tid] = s;
            __syncthreads();
            if (half == 0) {
                float rv = redf[tid] + redf[tid + 64] + linb[col];
                g_y[((size_t)t * BATCH + b) * IN + col] = rv;
                out[((size_t)b * PRED + t) * IN + col] = rv;
            }
        }
        release(round + 1); round++;
        // g_y rows for this b-tile come from projection CTAs [b0/2, b0/2+16)
        waitf(b0 >> 1, 16, round);
    }
}

extern "C" void kernel_launch(void* const* d_in, const int* in_sizes, int n_in,
                              void* d_out, int out_size) {
    const float* x    = (const float*)d_in[0];
    const float* eWih = (const float*)d_in[1];
    const float* eWhh = (const float*)d_in[2];
    const float* ebih = (const float*)d_in[3];
    const float* ebhh = (const float*)d_in[4];
    const float* dWih = (const float*)d_in[5];
    const float* dWhh = (const float*)d_in[6];
    const float* dbih = (const float*)d_in[7];
    const float* dbhh = (const float*)d_in[8];
    const float* linW = (const float*)d_in[9];
    const float* linb = (const float*)d_in[10];
    float* out = (float*)d_out;

    void* flagsPtr = nullptr;
    cudaGetSymbolAddress(&flagsPtr, g_flags);
    cudaMemsetAsync(flagsPtr, 0, sizeof(int) * NBLK, 0);

    cudaFuncSetAttribute(lstm_s2s_kernel,
                         cudaFuncAttributeMaxDynamicSharedMemorySize, SMEM_BYTES);

    lstm_s2s_kernel<<<NBLK, NTHR, SMEM_BYTES>>>(
        x, eWih, eWhh, ebih, ebhh, dWih, dWhh, dbih, dbhh, linW, linb, out);
}

// round 15
// speedup vs baseline: 2.0388x; 1.0699x over previous
#include <cuda_runtime.h>
#include <cstdint>

// ---------------------------------------------------------------------------
// Seq2seq BiLSTM (encoder 336 + autoregressive decoder 24), persistent kernel.
//
// Grid = 128 CTAs = 2 dirs x 4 batch-tiles(32) x 16 j-tiles(16), 256 thr/CTA.
// SPLIT-K: half0 = warps 0-3 (k 0..32 pre, 64..192 post), half1 = warps 4-7
// (k 32..64 pre, 192..320 post). Thread: 4 batch rows x 4 gates of one hidden
// unit (f32x2 gate pairs) over its K half.
// WARP-PAIR locality: warp p & p+4 share batch rows 8p..8p+8; all staging and
// the partial-accumulator exchange sync with named barrier (p+1, 64 threads).
// Flag wait is warp-local. One __syncthreads per round (flag release).
// Pointwise split: half0 finishes rows {0,1} of each 4-row group, half1 {2,3}.
// AS=332 (was 328): tb-row pair offset = 16 banks -> conflict-free A LDS.128.
// g_h double-buffered by parity; release/acquire flag protocol, 16-CTA groups.
// ---------------------------------------------------------------------------

#define NBLK 128
#define NTHR 256

namespace {
constexpr int BATCH = 128;
constexpr int SEQLEN = 336;
constexpr int PRED = 24;
constexpr int IN = 64;
constexpr int HID = 256;
constexpr int KTOT = IN + HID;          // 320
constexpr int WS = 68;                  // W smem row stride (floats)
constexpr int AS = 332;                 // A row stride: 4*AS % 32 banks = 16
constexpr int RED_U64 = 128 * 9;        // partial-acc exchange scratch
constexpr int SMEM_FLOATS = KTOT * WS + 32 * AS + 64 + RED_U64 * 2;
constexpr int SMEM_BYTES = SMEM_FLOATS * 4;   // 139008 B
}

__device__ float g_h[2][2 * BATCH * HID];       // [parity][dir*BATCH+b][HID]
__device__ float g_y[PRED * BATCH * IN];
__device__ int   g_flags[NBLK];

using u64 = unsigned long long;

__device__ __forceinline__ int ld_acq(const int* p) {
    int v;
    asm volatile("ld.global.acquire.gpu.b32 %0, [%1];" : "=r"(v) : "l"(p) : "memory");
    return v;
}
__device__ __forceinline__ void st_rel(int* p, int v) {
    asm volatile("st.global.release.gpu.b32 [%0], %1;" :: "l"(p), "r"(v) : "memory");
}
__device__ __forceinline__ u64 ffma2(u64 a, u64 b, u64 c) {
    u64 d;
    asm("fma.rn.f32x2 %0, %1, %2, %3;" : "=l"(d) : "l"(a), "l"(b), "l"(c));
    return d;
}
__device__ __forceinline__ u64 fadd2(u64 a, u64 b) {
    u64 d;
    asm("add.rn.f32x2 %0, %1, %2;" : "=l"(d) : "l"(a), "l"(b));
    return d;
}
__device__ __forceinline__ u64 pack2(float lo, float hi) {
    u64 d;
    asm("mov.b64 %0, {%1, %2};" : "=l"(d) : "f"(lo), "f"(hi));
    return d;
}
__device__ __forceinline__ void unpack2(float& lo, float& hi, u64 v) {
    asm("mov.b64 {%0, %1}, %2;" : "=f"(lo), "=f"(hi) : "l"(v));
}
__device__ __forceinline__ float fsig(float x) {
    return __fdividef(1.0f, 1.0f + __expf(-x));
}
__device__ __forceinline__ float ftanh(float x) {
    float ax = fabsf(x);
    float t = __expf(-2.0f * ax);
    float r = __fdividef(1.0f - t, 1.0f + t);
    return copysignf(r, x);
}

__device__ __forceinline__ void pairbar(int pair) {
    asm volatile("bar.sync %0, 64;" :: "r"(pair + 1) : "memory");
}
__device__ __forceinline__ void release(int v) {
    __syncthreads();
    if (threadIdx.x == 0) st_rel(&g_flags[blockIdx.x], v);
}
__device__ __forceinline__ void waitf(int base, int cnt, int v) {
    if (threadIdx.x < cnt) {
        const int* p = &g_flags[base + threadIdx.x];
        while (ld_acq(p) < v) { }
    }
    __syncthreads();
}
__device__ __forceinline__ void pollflag(int idx, int v) {
    const int* p = &g_flags[idx];
    while (ld_acq(p) < v) { }
}

// W slice -> SMEM: Wsm[k*WS + jj*4 + g], source row = g*256 + j0 + jj.
__device__ void load_phase_weights(float* Wsm, float* bsum,
                                   const float* __restrict__ Wih,
                                   const float* __restrict__ Whh,
                                   const float* __restrict__ bih,
                                   const float* __restrict__ bhh,
                                   int d, int j0) {
    for (int idx = threadIdx.x; idx < 64 * KTOT; idx += NTHR) {
        int c = idx / KTOT;
        int k = idx - c * KTOT;
        int jj = c >> 2, g = c & 3;
        int row = g * 256 + j0 + jj;
        float v = (k < IN) ? Wih[(d * 1024 + row) * IN + k]
                           : Whh[(d * 1024 + row) * HID + (k - IN)];
        Wsm[k * WS + c] = v;
    }
    for (int c = threadIdx.x; c < 64; c += NTHR) {
        int jj = c >> 2, g = c & 3;
        int row = g * 256 + j0 + jj;
        bsum[c] = bih[d * 1024 + row] + bhh[d * 1024 + row];
    }
}

// Packed f32x2 GEMM over k range [k0,k1); 4 rows x (i,f),(g,o) pairs.
__device__ __forceinline__ void gemm_span(const float* Asm, const float* Wsm,
                                          int tj, int tb, int k0, int k1,
                                          u64 acc[4][2]) {
    const float* A0 = Asm + (tb * 4) * AS;
#pragma unroll 4
    for (int k = k0; k < k1; k += 4) {
        float4 a0 = *(const float4*)(A0 + k);
        float4 a1 = *(const float4*)(A0 + AS + k);
        float4 a2 = *(const float4*)(A0 + 2 * AS + k);
        float4 a3 = *(const float4*)(A0 + 3 * AS + k);
        float av[4][4] = {{a0.x, a0.y, a0.z, a0.w},
                          {a1.x, a1.y, a1.z, a1.w},
                          {a2.x, a2.y, a2.z, a2.w},
                          {a3.x, a3.y, a3.z, a3.w}};
#pragma unroll
        for (int kk = 0; kk < 4; kk++) {
            const u64* Wq = (const u64*)(Wsm + (k + kk) * WS) + tj * 2;
            u64 w01 = Wq[0];
            u64 w23 = Wq[1];
#pragma unroll
            for (int bi = 0; bi < 4; bi++) {
                u64 ad = pack2(av[bi][kk], av[bi][kk]);
                acc[bi][0] = ffma2(ad, w01, acc[bi][0]);
                acc[bi][1] = ffma2(ad, w23, acc[bi][1]);
            }
        }
    }
}

// One LSTM step; pair-local staging + split-K + split pointwise.
__device__ __forceinline__ void cell_step(const float* __restrict__ src,
                                          int rowStride, int d, int b0, int j0,
                                          const float* __restrict__ hsrc,
                                          float* __restrict__ hdst,
                                          const float* Wsm, float* Asm,
                                          u64* redsm, const float* bsum,
                                          float c_reg[2], int round, int gbase,
                                          int hg, int pair, int ptid, int lane,
                                          int tid7, int tj, int tb) {
    // ---- 1. stage x rows [8*pair, 8*pair+8), cols 0..16 f4 (pair-local)
#pragma unroll
    for (int it = 0; it < 2; it++) {
        int idx = ptid + it * 64;                  // 0..127
        int row = pair * 8 + (idx >> 4);
        int f4 = idx & 15;
        float4 v = __ldcg((const float4*)(src + (size_t)(b0 + row) * rowStride) + f4);
        *(float4*)(Asm + row * AS + f4 * 4) = v;
    }
    pairbar(pair);

    // ---- 2. acc init + pre-wait x-GEMM (half0 k0..32, half1 k32..64)
    u64 acc[4][2];
    if (hg == 0) {
        float4 bv = *(const float4*)(bsum + tj * 4);
        u64 b01 = pack2(bv.x, bv.y);
        u64 b23 = pack2(bv.z, bv.w);
#pragma unroll
        for (int bi = 0; bi < 4; bi++) { acc[bi][0] = b01; acc[bi][1] = b23; }
        gemm_span(Asm, Wsm, tj, tb, 0, 32, acc);
    } else {
#pragma unroll
        for (int bi = 0; bi < 4; bi++) { acc[bi][0] = 0ull; acc[bi][1] = 0ull; }
        gemm_span(Asm, Wsm, tj, tb, 32, IN, acc);
    }

    // ---- 3. warp-local wait on the 16 group flags
    if (lane < 16) pollflag(gbase + lane, round);
    __syncwarp();

    // ---- 4. stage h rows [8*pair, 8*pair+8), 64 f4 per row (pair-local)
    float4 v[8];
#pragma unroll
    for (int u = 0; u < 8; u++) {
        int idx = ptid + u * 64;                   // 0..511
        int row8 = idx >> 6;
        int slot = idx & 63;
        v[u] = __ldcg((const float4*)(hsrc +
                (size_t)((d << 7) + b0 + pair * 8 + row8) * HID) + slot);
    }
#pragma unroll
    for (int u = 0; u < 8; u++) {
        int idx = ptid + u * 64;
        int row8 = idx >> 6;
        int slot = idx & 63;
        *(float4*)(Asm + (pair * 8 + row8) * AS + IN + slot * 4) = v[u];
    }
    pairbar(pair);

    // ---- 5. h-GEMM (half0 k64..192, half1 k192..320)
    if (hg == 0) gemm_span(Asm, Wsm, tj, tb, IN, IN + 128, acc);
    else         gemm_span(Asm, Wsm, tj, tb, IN + 128, KTOT, acc);

    // ---- 6. symmetric partial exchange: half0 gives rows {2,3}, half1 {0,1}
    u64* r = redsm + (size_t)tid7 * 9;
    if (hg == 0) {
        r[0] = acc[2][0]; r[1] = acc[2][1];
        r[2] = acc[3][0]; r[3] = acc[3][1];
    } else {
        r[4] = acc[0][0]; r[5] = acc[0][1];
        r[6] = acc[1][0]; r[7] = acc[1][1];
    }
    pairbar(pair);

    // ---- 7. pointwise on own 2 rows; h -> next-parity buffer
    int j = j0 + tj;
#pragma unroll
    for (int bi = 0; bi < 2; bi++) {
        u64 s01, s23;
        int row;
        if (hg == 0) {
            s01 = fadd2(acc[bi][0], r[4 + bi * 2 + 0]);
            s23 = fadd2(acc[bi][1], r[4 + bi * 2 + 1]);
            row = tb * 4 + bi;
        } else {
            s01 = fadd2(acc[2 + bi][0], r[bi * 2 + 0]);
            s23 = fadd2(acc[2 + bi][1], r[bi * 2 + 1]);
            row = tb * 4 + 2 + bi;
        }
        float gi, gf, gg, go;
        unpack2(gi, gf, s01);
        unpack2(gg, go, s23);
        float cn = fsig(gf) * c_reg[bi] + fsig(gi) * ftanh(gg);
        float hn = fsig(go) * ftanh(cn);
        c_reg[bi] = cn;
        hdst[(size_t)((d << 7) + b0 + row) * HID + j] = hn;
    }
}

__global__ void __launch_bounds__(NTHR, 1)
lstm_s2s_kernel(const float* __restrict__ x,
                const float* __restrict__ eWih, const float* __restrict__ eWhh,
                const float* __restrict__ ebih, const float* __restrict__ ebhh,
                const float* __restrict__ dWih, const float* __restrict__ dWhh,
                const float* __restrict__ dbih, const float* __restrict__ dbhh,
                const float* __restrict__ linW, const float* __restrict__ linb,
                float* __restrict__ out) {
    extern __shared__ float smem[];
    float* Wsm  = smem;                        // [320][68]
    float* Asm  = Wsm + KTOT * WS;             // [32][332]
    float* bsum = Asm + 32 * AS;               // [64]
    u64*   redsm = (u64*)(bsum + 64);          // [128][9] u64
    float* redf = (float*)redsm;               // projection scratch

    const int ct = blockIdx.x;
    const int d = ct >> 6;
    const int rem = ct & 63;
    const int b0 = (rem >> 4) * 32;
    const int j0 = (rem & 15) * 16;
    const int gbase = ct & ~15;                // 16 CTAs sharing (dir, b-tile)
    const int tid = threadIdx.x;
    const int hg = tid >> 7;                   // K-half
    const int tid7 = tid & 127;
    const int lane = tid & 31;
    const int pair = (tid >> 5) & 3;           // warp-pair id
    const int ptid = lane + (hg << 5);         // 0..63 within pair
    const int tj = tid7 & 15;
    const int tb = tid7 >> 4;                  // 0..7, 4 rows each

    float c_reg[2] = {0.f, 0.f};
    int hr = 0;

    // fresh state every replay: zero own h slice in buffer 0
    for (int idx = tid; idx < 32 * 16; idx += NTHR) {
        int bb = idx >> 4, jj = idx & 15;
        g_h[0][(size_t)((d << 7) + b0 + bb) * HID + j0 + jj] = 0.f;
    }
    release(1);
    int round = 1;

    load_phase_weights(Wsm, bsum, eWih, eWhh, ebih, ebhh, d, j0);
    __syncthreads();

    // ===== encoder =====
    for (int r = 0; r < SEQLEN; r++) {
        int t = (d == 0) ? r : (SEQLEN - 1 - r);
        cell_step(x + t * IN, SEQLEN * IN, d, b0, j0,
                  g_h[hr & 1], g_h[(hr + 1) & 1],
                  Wsm, Asm, redsm, bsum, c_reg, round, gbase,
                  hg, pair, ptid, lane, tid7, tj, tb);
        hr++;
        release(round + 1); round++;
    }

    // ===== switch to decoder weights =====
    load_phase_weights(Wsm, bsum, dWih, dWhh, dbih, dbhh, d, j0);
    __syncthreads();

    // ===== decoder: 24 autoregressive iterations =====
    for (int t = 0; t < PRED; t++) {
        int L = (t == 0) ? 1 : t;
        for (int s = 0; s < L; s++) {
            const float* src;
            int stride;
            if (t == 0) {
                src = x + (SEQLEN - 1) * IN;       // x[:, -1, :]
                stride = SEQLEN * IN;
            } else {
                int yi = (d == 0) ? s : (L - 1 - s);
                src = g_y + (size_t)yi * BATCH * IN;
                stride = IN;
            }
            cell_step(src, stride, d, b0, j0,
                      g_h[hr & 1], g_h[(hr + 1) & 1],
                      Wsm, Asm, redsm, bsum, c_reg, round, gbase,
                      hg, pair, ptid, lane, tid7, tj, tb);
            hr++;
            release(round + 1); round++;
        }

        // ---- projection (CTAs 0..63): y = concat(hF,hB) @ linW^T + linb
        if (ct < 64) {
            if (tid < 32) {                        // producers of this b-tile
                int base = (ct >> 4) * 16;
                pollflag(base + (tid & 15) + ((tid & 16) ? 64 : 0), round);
            }
            __syncthreads();
            const float* hb = g_h[hr & 1];
            int bsel = tid >> 7;                   // 0..1
            int half = (tid >> 6) & 1;             // 0 = fwd h, 1 = bwd h
            int col  = tid & 63;
            int b = (ct << 1) + bsel;
            const float4* w4 = (const float4*)(linW + col * (2 * HID)) + half * (HID / 4);
            const float4* hv = (const float4*)(hb + (size_t)(half * BATCH + b) * HID);
            float s = 0.f;
#pragma unroll 8
            for (int q = 0; q < HID / 4; q++) {
                float4 f = __ldcg(hv + q);
                float4 w = __ldg(w4 + q);
                s += f.x * w.x + f.y * w.y + f.z * w.z + f.w * w.w;
            }
            redf[tid] = s;
            __syncthreads();
            if (half == 0) {
                float rv = redf[tid] + redf[tid + 64] + linb[col];
                g_y[((size_t)t * BATCH + b) * IN + col] = rv;
                out[((size_t)b * PRED + t) * IN + col] = rv;
            }
        }
        release(round + 1); round++;
        // g_y rows for this b-tile come from projection CTAs [b0/2, b0/2+16)
        waitf(b0 >> 1, 16, round);
    }
}

extern "C" void kernel_launch(void* const* d_in, const int* in_sizes, int n_in,
                              void* d_out, int out_size) {
    const float* x    = (const float*)d_in[0];
    const float* eWih = (const float*)d_in[1];
    const float* eWhh = (const float*)d_in[2];
    const float* ebih = (const float*)d_in[3];
    const float* ebhh = (const float*)d_in[4];
    const float* dWih = (const float*)d_in[5];
    const float* dWhh = (const float*)d_in[6];
    const float* dbih = (const float*)d_in[7];
    const float* dbhh = (const float*)d_in[8];
    const float* linW = (const float*)d_in[9];
    const float* linb = (const float*)d_in[10];
    float* out = (float*)d_out;

    void* flagsPtr = nullptr;
    cudaGetSymbolAddress(&flagsPtr, g_flags);
    cudaMemsetAsync(flagsPtr, 0, sizeof(int) * NBLK, 0);

    cudaFuncSetAttribute(lstm_s2s_kernel,
                         cudaFuncAttributeMaxDynamicSharedMemorySize, SMEM_BYTES);

    lstm_s2s_kernel<<<NBLK, NTHR, SMEM_BYTES>>>(
        x, eWih, eWhh, ebih, ebhh, dWih, dWhh, dbih, dbhh, linW, linb, out);
}